// round 5
// baseline (speedup 1.0000x reference)
#include <cuda_runtime.h>
#include <math.h>
#include <stdint.h>

#ifndef M_PI
#define M_PI 3.14159265358979323846
#endif

// Problem shape (fixed by setup_inputs)
#define BB 2
#define NV 4
#define HH 256
#define WW 512
#define HWSZ (HH * WW)            // 131072
#define PP (NV * HWSZ)            // 524288 points per batch
#define TOTAL (BB * PP)           // 1048576 points total
#define NCH 24

#define VOXEL_SIZE 0.1f
#define CONF_W 0.7f
#define OPAC_W 0.3f
#define CONF_THRESH 0.1f
#define OPAC_THRESH 0.01f

#define TABLE_BITS 20
#define TABLE_SIZE (1u << TABLE_BITS)
#define TABLE_MASK (TABLE_SIZE - 1u)
#define EMPTY_KEY 0xFFFFFFFFu
#define INV_SLOT 0xFFFFFFFFu

// Scratch (no runtime allocation allowed -> __device__ globals)
__device__ unsigned int       g_keys[TABLE_SIZE];   // 4 MB
__device__ unsigned long long g_max1[TABLE_SIZE];   // 8 MB
__device__ unsigned long long g_max2[TABLE_SIZE];   // 8 MB
__device__ unsigned int       g_slot[TOTAL];        // 4 MB

// ---------------------------------------------------------------------------

// 4 independent 16-byte stores per thread (grid-stride layout) -> high MLP.
#define KEYS16  (TABLE_SIZE / 4)                    // uint4 chunks for g_keys
#define MAX16   (TABLE_SIZE / 2)                    // ulonglong2 chunks per max array
#define CLEAR16 (KEYS16 + 2 * MAX16)                // 1.25M chunks
#define CLEAR_THREADS ((CLEAR16 + 3) / 4)
__global__ void __launch_bounds__(256) clear_kernel() {
    unsigned t = blockIdx.x * blockDim.x + threadIdx.x;
#pragma unroll
    for (int k = 0; k < 4; k++) {
        unsigned i = t + (unsigned)k * CLEAR_THREADS;
        if (i < KEYS16) {
            reinterpret_cast<uint4*>(g_keys)[i] =
                make_uint4(EMPTY_KEY, EMPTY_KEY, EMPTY_KEY, EMPTY_KEY);
        } else if (i < KEYS16 + MAX16) {
            ulonglong2 z; z.x = 0ull; z.y = 0ull;
            reinterpret_cast<ulonglong2*>(g_max1)[i - KEYS16] = z;
        } else if (i < CLEAR16) {
            ulonglong2 z; z.x = 0ull; z.y = 0ull;
            reinterpret_cast<ulonglong2*>(g_max2)[i - (KEYS16 + MAX16)] = z;
        }
    }
}

// Find (or claim) the table slot for voxel `key`.
__device__ __forceinline__ unsigned probe_slot(unsigned key) {
    unsigned h = (key * 2654435761u) >> (32 - TABLE_BITS);
    for (;;) {
        unsigned cur = g_keys[h];
        if (cur == key) return h;
        if (cur == EMPTY_KEY) {
            unsigned prev = atomicCAS(&g_keys[h], EMPTY_KEY, key);
            if (prev == EMPTY_KEY || prev == key) return h;
        }
        h = (h + 1u) & TABLE_MASK;
    }
}

// Identical arithmetic to the R1 passing kernel (keep numerics stable).
__device__ __forceinline__ void compute_point(
    int g, const float* __restrict__ depth, const float* __restrict__ opac,
    const float* __restrict__ conf, const float* __restrict__ poses,
    bool& valid, unsigned& key, unsigned long long& packed,
    float& mx, float& my, float& mz)
{
    int b  = g / PP;
    int p  = g - b * PP;
    int n  = p / HWSZ;
    int hw = p - n * HWSZ;
    int h  = hw / WW;
    int w  = hw - h * WW;

    float d = depth[g];
    float c = conf[g];
    float o = opac[g];
    valid = (c > CONF_THRESH) && (o > OPAC_THRESH);

    const float fx = (float)((double)WW / (2.0 * M_PI));
    const float fy = (float)(-(double)HH / M_PI);
    float lon = ((float)w + 0.5f - (float)(WW / 2)) / fx;
    float lat = ((float)h + 0.5f - (float)(HH / 2)) / fy;
    float slat, clat, slon, clon;
    sincosf(lat, &slat, &clat);
    sincosf(lon, &slon, &clon);
    float dx = clat * slon;
    float dy = -slat;
    float dz = clat * clon;

    float px = d * dx, py = d * dy, pz = d * dz;

    const float* M = poses + (size_t)(b * NV + n) * 16;
    mx = M[0] * px + M[1] * py + M[2]  * pz + M[3];
    my = M[4] * px + M[5] * py + M[6]  * pz + M[7];
    mz = M[8] * px + M[9] * py + M[10] * pz + M[11];

    int vx = min(max((int)floorf(mx / VOXEL_SIZE) + 512, 0), 1023);
    int vy = min(max((int)floorf(my / VOXEL_SIZE) + 512, 0), 1023);
    int vz = min(max((int)floorf(mz / VOXEL_SIZE) + 512, 0), 1023);
    unsigned vid = ((unsigned)vx << 20) | ((unsigned)vy << 10) | (unsigned)vz;
    key = ((unsigned)b << 30) | vid;

    float score = CONF_W * c + OPAC_W * o;
    packed = ((unsigned long long)__float_as_uint(score) << 32)
           | (unsigned long long)(0xFFFFFFFFu - (unsigned)p);
}

// Streaming top-2: one atomicMax with return + one fire-and-forget RED.MAX.
__global__ void __launch_bounds__(256) pass1_kernel(
    const float* __restrict__ depth, const float* __restrict__ opac,
    const float* __restrict__ conf,  const float* __restrict__ poses)
{
    int g = blockIdx.x * blockDim.x + threadIdx.x;
    if (g >= TOTAL) return;

    bool valid; unsigned key; unsigned long long pk;
    float mx, my, mz;
    compute_point(g, depth, opac, conf, poses, valid, key, pk, mx, my, mz);

    if (!valid) { g_slot[g] = INV_SLOT; return; }

    unsigned slot = probe_slot(key);
    unsigned long long old = atomicMax(&g_max1[slot], pk);
    unsigned long long v = (pk < old) ? pk : old;   // displaced value
    if (v != 0ull)
        atomicMax(&g_max2[slot], v);                // result unused -> RED

    g_slot[g] = slot;
}

// 4 points per thread; all channel gathers as float4 (quads never cross an
// image row since W % 4 == 0). Random max reads issued up-front (MLP 8).
__global__ void __launch_bounds__(256) pass3_kernel(
    const float* __restrict__ depth, const float* __restrict__ cov,
    const float* __restrict__ rot,   const float* __restrict__ opac,
    const float* __restrict__ sh,    const float* __restrict__ conf,
    const float* __restrict__ poses, float* __restrict__ out,
    int write_sel, size_t sel_off)
{
    int q = blockIdx.x * blockDim.x + threadIdx.x;   // grid sized TOTAL/4
    int g0 = q << 2;

    int b   = g0 / PP;
    int p0  = g0 - b * PP;
    int n   = p0 / HWSZ;
    int hw0 = p0 - n * HWSZ;
    int h   = hw0 / WW;
    int w0  = hw0 - h * WW;

    float4 d4 = *reinterpret_cast<const float4*>(depth + g0);
    float4 c4 = *reinterpret_cast<const float4*>(conf  + g0);
    float4 o4 = *reinterpret_cast<const float4*>(opac  + g0);
    float dd[4] = {d4.x, d4.y, d4.z, d4.w};
    float cc[4] = {c4.x, c4.y, c4.z, c4.w};
    float oo[4] = {o4.x, o4.y, o4.z, o4.w};

    // Selection flags (identical packing/semantics to pass1).
    uint4 sl4 = *reinterpret_cast<const uint4*>(g_slot + g0);
    unsigned slots[4] = {sl4.x, sl4.y, sl4.z, sl4.w};
    unsigned long long m1[4], m2[4];
#pragma unroll
    for (int k = 0; k < 4; k++) {
        unsigned slot = slots[k];
        if (slot != INV_SLOT) {
            m1[k] = __ldg(&g_max1[slot]);
            m2[k] = __ldg(&g_max2[slot]);
        } else { m1[k] = 1ull; m2[k] = 1ull; }   // never matches a packed key
    }

    const float fx = (float)((double)WW / (2.0 * M_PI));
    const float fy = (float)(-(double)HH / M_PI);
    float lat = ((float)h + 0.5f - (float)(HH / 2)) / fy;
    float slat, clat;
    sincosf(lat, &slat, &clat);

    const float* M = poses + (size_t)(b * NV + n) * 16;
    float M0 = M[0], M1 = M[1], M2 = M[2],  M3 = M[3];
    float M4 = M[4], M5 = M[5], M6 = M[6],  M7 = M[7];
    float M8 = M[8], M9 = M[9], M10 = M[10], M11 = M[11];

    float s[4], mxa[4], mya[4], mza[4];
#pragma unroll
    for (int k = 0; k < 4; k++) {
        float d = dd[k], c = cc[k], o = oo[k];
        float lon = ((float)(w0 + k) + 0.5f - (float)(WW / 2)) / fx;
        float slon, clon;
        sincosf(lon, &slon, &clon);
        float dx = clat * slon;
        float dy = -slat;
        float dz = clat * clon;
        float px = d * dx, py = d * dy, pz = d * dz;
        mxa[k] = M0 * px + M1 * py + M2  * pz + M3;
        mya[k] = M4 * px + M5 * py + M6  * pz + M7;
        mza[k] = M8 * px + M9 * py + M10 * pz + M11;

        float score = CONF_W * c + OPAC_W * o;
        unsigned long long pk =
            ((unsigned long long)__float_as_uint(score) << 32)
            | (unsigned long long)(0xFFFFFFFFu - (unsigned)(p0 + k));
        s[k] = (pk == m1[k] || pk == m2[k]) ? 1.0f : 0.0f;
    }

    size_t bn     = (size_t)(b * NV + n);
    size_t base_c = (bn * 3)  * HWSZ + hw0;
    size_t base_r = (bn * 4)  * HWSZ + hw0;
    size_t base_s = (bn * 12) * HWSZ + hw0;

    float4* dst = reinterpret_cast<float4*>(out + (size_t)g0 * NCH);
    // Row layout per point (24 floats): mx my mz cv0 | cv1 cv2 r0 r1 |
    //                                   r2 r3 op sh0 | sh1..4 | sh5..8 | sh9 sh10 sh11 cf
    {
        // Wave 1: cov(3) + rot(4) + sh0 -> row groups 0,1,2
        float4 cv0 = __ldg(reinterpret_cast<const float4*>(cov + base_c));
        float4 cv1 = __ldg(reinterpret_cast<const float4*>(cov + base_c + HWSZ));
        float4 cv2 = __ldg(reinterpret_cast<const float4*>(cov + base_c + 2 * (size_t)HWSZ));
        float4 r0  = __ldg(reinterpret_cast<const float4*>(rot + base_r));
        float4 r1  = __ldg(reinterpret_cast<const float4*>(rot + base_r + HWSZ));
        float4 r2  = __ldg(reinterpret_cast<const float4*>(rot + base_r + 2 * (size_t)HWSZ));
        float4 r3  = __ldg(reinterpret_cast<const float4*>(rot + base_r + 3 * (size_t)HWSZ));
        float4 s0  = __ldg(reinterpret_cast<const float4*>(sh + base_s));
        float cv0a[4] = {cv0.x, cv0.y, cv0.z, cv0.w};
        float cv1a[4] = {cv1.x, cv1.y, cv1.z, cv1.w};
        float cv2a[4] = {cv2.x, cv2.y, cv2.z, cv2.w};
        float r0a[4]  = {r0.x, r0.y, r0.z, r0.w};
        float r1a[4]  = {r1.x, r1.y, r1.z, r1.w};
        float r2a[4]  = {r2.x, r2.y, r2.z, r2.w};
        float r3a[4]  = {r3.x, r3.y, r3.z, r3.w};
        float s0a[4]  = {s0.x, s0.y, s0.z, s0.w};
#pragma unroll
        for (int k = 0; k < 4; k++) {
            float sk = s[k];
            __stcs(dst + k * 6 + 0, make_float4(mxa[k] * sk, mya[k] * sk,
                                                mza[k] * sk, cv0a[k] * sk));
            __stcs(dst + k * 6 + 1, make_float4(cv1a[k] * sk, cv2a[k] * sk,
                                                r0a[k] * sk, r1a[k] * sk));
            __stcs(dst + k * 6 + 2, make_float4(r2a[k] * sk, r3a[k] * sk,
                                                oo[k] * sk, s0a[k] * sk));
        }
    }
    {
        // Wave 2: sh1..8 -> row groups 3,4
        float4 q1 = __ldg(reinterpret_cast<const float4*>(sh + base_s + 1 * (size_t)HWSZ));
        float4 q2 = __ldg(reinterpret_cast<const float4*>(sh + base_s + 2 * (size_t)HWSZ));
        float4 q3 = __ldg(reinterpret_cast<const float4*>(sh + base_s + 3 * (size_t)HWSZ));
        float4 q4 = __ldg(reinterpret_cast<const float4*>(sh + base_s + 4 * (size_t)HWSZ));
        float4 q5 = __ldg(reinterpret_cast<const float4*>(sh + base_s + 5 * (size_t)HWSZ));
        float4 q6 = __ldg(reinterpret_cast<const float4*>(sh + base_s + 6 * (size_t)HWSZ));
        float4 q7 = __ldg(reinterpret_cast<const float4*>(sh + base_s + 7 * (size_t)HWSZ));
        float4 q8 = __ldg(reinterpret_cast<const float4*>(sh + base_s + 8 * (size_t)HWSZ));
        float a1[4] = {q1.x, q1.y, q1.z, q1.w};
        float a2[4] = {q2.x, q2.y, q2.z, q2.w};
        float a3[4] = {q3.x, q3.y, q3.z, q3.w};
        float a4[4] = {q4.x, q4.y, q4.z, q4.w};
        float a5[4] = {q5.x, q5.y, q5.z, q5.w};
        float a6[4] = {q6.x, q6.y, q6.z, q6.w};
        float a7[4] = {q7.x, q7.y, q7.z, q7.w};
        float a8[4] = {q8.x, q8.y, q8.z, q8.w};
#pragma unroll
        for (int k = 0; k < 4; k++) {
            float sk = s[k];
            __stcs(dst + k * 6 + 3, make_float4(a1[k] * sk, a2[k] * sk,
                                                a3[k] * sk, a4[k] * sk));
            __stcs(dst + k * 6 + 4, make_float4(a5[k] * sk, a6[k] * sk,
                                                a7[k] * sk, a8[k] * sk));
        }
    }
    {
        // Wave 3: sh9..11 + conf -> row group 5
        float4 q9  = __ldg(reinterpret_cast<const float4*>(sh + base_s + 9  * (size_t)HWSZ));
        float4 q10 = __ldg(reinterpret_cast<const float4*>(sh + base_s + 10 * (size_t)HWSZ));
        float4 q11 = __ldg(reinterpret_cast<const float4*>(sh + base_s + 11 * (size_t)HWSZ));
        float a9[4]  = {q9.x, q9.y, q9.z, q9.w};
        float a10[4] = {q10.x, q10.y, q10.z, q10.w};
        float a11[4] = {q11.x, q11.y, q11.z, q11.w};
#pragma unroll
        for (int k = 0; k < 4; k++) {
            float sk = s[k];
            __stcs(dst + k * 6 + 5, make_float4(a9[k] * sk, a10[k] * sk,
                                                a11[k] * sk, cc[k] * sk));
        }
    }

    if (write_sel)
        __stcs(reinterpret_cast<float4*>(out + sel_off + (size_t)g0),
               make_float4(s[0], s[1], s[2], s[3]));
}

// ---------------------------------------------------------------------------

extern "C" void kernel_launch(void* const* d_in, const int* in_sizes, int n_in,
                              void* d_out, int out_size) {
    const float* depth = (const float*)d_in[0];
    const float* cov   = (const float*)d_in[1];
    const float* rot   = (const float*)d_in[2];
    const float* opac  = (const float*)d_in[3];
    const float* sh    = (const float*)d_in[4];
    const float* conf  = (const float*)d_in[5];
    const float* poses = (const float*)d_in[6];
    float* out = (float*)d_out;

    size_t featN = (size_t)TOTAL * NCH;
    int write_sel = ((size_t)out_size >= featN + (size_t)TOTAL) ? 1 : 0;

    const int T = 256;
    clear_kernel<<<(CLEAR_THREADS + T - 1) / T, T>>>();
    pass1_kernel<<<(TOTAL + T - 1) / T, T>>>(depth, opac, conf, poses);
    pass3_kernel<<<(TOTAL / 4 + T - 1) / T, T>>>(depth, cov, rot, opac, sh,
                                                 conf, poses, out, write_sel,
                                                 featN);
}

// round 6
// speedup vs baseline: 1.4964x; 1.4964x over previous
#include <cuda_runtime.h>
#include <math.h>
#include <stdint.h>

#ifndef M_PI
#define M_PI 3.14159265358979323846
#endif

// Problem shape (fixed by setup_inputs)
#define BB 2
#define NV 4
#define HH 256
#define WW 512
#define HWSZ (HH * WW)            // 131072
#define PP (NV * HWSZ)            // 524288 points per batch
#define TOTAL (BB * PP)           // 1048576 points total
#define NCH 24

#define VOXEL_SIZE 0.1f
#define CONF_W 0.7f
#define OPAC_W 0.3f
#define CONF_THRESH 0.1f
#define OPAC_THRESH 0.01f

#define TABLE_BITS 21
#define TABLE_SIZE (1u << TABLE_BITS)
#define TABLE_MASK (TABLE_SIZE - 1u)
#define EMPTY_KEY 0xFFFFFFFFu
#define INV_SLOT 0xFFFFFFFFu

// Scratch (no runtime allocation allowed -> __device__ globals)
__device__ unsigned int       g_keys[TABLE_SIZE];   // 8 MB
__device__ unsigned long long g_max1[TABLE_SIZE];   // 16 MB
__device__ unsigned long long g_max2[TABLE_SIZE];   // 16 MB
__device__ unsigned int       g_slot[TOTAL];        // 4 MB

// ---------------------------------------------------------------------------

// 4 independent 16-byte stores per thread -> high MLP, few dependent chains.
#define KEYS16  (TABLE_SIZE / 4)                    // uint4 chunks for g_keys
#define MAX16   (TABLE_SIZE / 2)                    // ulonglong2 chunks per max array
#define CLEAR16 (KEYS16 + 2 * MAX16)
#define CLEAR_THREADS ((CLEAR16 + 3) / 4)
__global__ void __launch_bounds__(256) clear_kernel() {
    unsigned t = blockIdx.x * blockDim.x + threadIdx.x;
#pragma unroll
    for (int k = 0; k < 4; k++) {
        unsigned i = t + (unsigned)k * CLEAR_THREADS;
        if (i < KEYS16) {
            reinterpret_cast<uint4*>(g_keys)[i] =
                make_uint4(EMPTY_KEY, EMPTY_KEY, EMPTY_KEY, EMPTY_KEY);
        } else if (i < KEYS16 + MAX16) {
            ulonglong2 z; z.x = 0ull; z.y = 0ull;
            reinterpret_cast<ulonglong2*>(g_max1)[i - KEYS16] = z;
        } else if (i < CLEAR16) {
            ulonglong2 z; z.x = 0ull; z.y = 0ull;
            reinterpret_cast<ulonglong2*>(g_max2)[i - (KEYS16 + MAX16)] = z;
        }
    }
}

// Find (or claim) the table slot for voxel `key`.
__device__ __forceinline__ unsigned probe_slot(unsigned key) {
    unsigned h = (key * 2654435761u) >> (32 - TABLE_BITS);
    for (;;) {
        unsigned cur = g_keys[h];
        if (cur == key) return h;
        if (cur == EMPTY_KEY) {
            unsigned prev = atomicCAS(&g_keys[h], EMPTY_KEY, key);
            if (prev == EMPTY_KEY || prev == key) return h;
        }
        h = (h + 1u) & TABLE_MASK;
    }
}

// Packed (score, index) key — ONE definition so pass1/pass3 agree bit-exactly.
__device__ __forceinline__ unsigned long long pack_key(float c, float o,
                                                       unsigned p) {
    float score = __fmaf_rn(CONF_W, c, __fmul_rn(OPAC_W, o));
    return ((unsigned long long)__float_as_uint(score) << 32)
         | (unsigned long long)(0xFFFFFFFFu - p);
}

// Identical arithmetic to the R1 passing kernel (keep numerics stable).
__device__ __forceinline__ void compute_point(
    int g, const float* __restrict__ depth, const float* __restrict__ opac,
    const float* __restrict__ conf, const float* __restrict__ poses,
    bool& valid, unsigned& key, unsigned long long& packed,
    float& mx, float& my, float& mz)
{
    int b  = g / PP;
    int p  = g - b * PP;
    int n  = p / HWSZ;
    int hw = p - n * HWSZ;
    int h  = hw / WW;
    int w  = hw - h * WW;

    float d = depth[g];
    float c = conf[g];
    float o = opac[g];
    valid = (c > CONF_THRESH) && (o > OPAC_THRESH);

    const float fx = (float)((double)WW / (2.0 * M_PI));
    const float fy = (float)(-(double)HH / M_PI);
    float lon = ((float)w + 0.5f - (float)(WW / 2)) / fx;
    float lat = ((float)h + 0.5f - (float)(HH / 2)) / fy;
    float slat, clat, slon, clon;
    sincosf(lat, &slat, &clat);
    sincosf(lon, &slon, &clon);
    float dx = clat * slon;
    float dy = -slat;
    float dz = clat * clon;

    float px = d * dx, py = d * dy, pz = d * dz;

    const float* M = poses + (size_t)(b * NV + n) * 16;
    mx = M[0] * px + M[1] * py + M[2]  * pz + M[3];
    my = M[4] * px + M[5] * py + M[6]  * pz + M[7];
    mz = M[8] * px + M[9] * py + M[10] * pz + M[11];

    int vx = min(max((int)floorf(mx / VOXEL_SIZE) + 512, 0), 1023);
    int vy = min(max((int)floorf(my / VOXEL_SIZE) + 512, 0), 1023);
    int vz = min(max((int)floorf(mz / VOXEL_SIZE) + 512, 0), 1023);
    unsigned vid = ((unsigned)vx << 20) | ((unsigned)vy << 10) | (unsigned)vz;
    key = ((unsigned)b << 30) | vid;

    packed = pack_key(c, o, (unsigned)p);
}

// Streaming top-2: one atomicMax with return + one fire-and-forget RED.MAX.
// Every value except the running max is attempted into max2, so after all
// inserts max2 == second maximum. No CAS retry loops.
__global__ void __launch_bounds__(256) pass1_kernel(
    const float* __restrict__ depth, const float* __restrict__ opac,
    const float* __restrict__ conf,  const float* __restrict__ poses)
{
    int g = blockIdx.x * blockDim.x + threadIdx.x;
    if (g >= TOTAL) return;

    bool valid; unsigned key; unsigned long long pk;
    float mx, my, mz;
    compute_point(g, depth, opac, conf, poses, valid, key, pk, mx, my, mz);

    if (!valid) { g_slot[g] = INV_SLOT; return; }

    unsigned slot = probe_slot(key);
    unsigned long long old = atomicMax(&g_max1[slot], pk);
    unsigned long long v = (pk < old) ? pk : old;   // displaced value
    if (v != 0ull)
        atomicMax(&g_max2[slot], v);                // result unused -> RED

    g_slot[g] = slot;
}

__global__ void __launch_bounds__(256) pass3_kernel(
    const float* __restrict__ depth, const float* __restrict__ cov,
    const float* __restrict__ rot,   const float* __restrict__ opac,
    const float* __restrict__ sh,    const float* __restrict__ conf,
    const float* __restrict__ poses, float* __restrict__ out,
    int write_sel, size_t sel_off)
{
    int g = blockIdx.x * blockDim.x + threadIdx.x;
    if (g >= TOTAL) return;

    bool valid; unsigned key; unsigned long long packed;
    float mx, my, mz;
    compute_point(g, depth, opac, conf, poses, valid, key, packed, mx, my, mz);

    float s = 0.0f;
    unsigned slot = g_slot[g];
    if (slot != INV_SLOT) {
        if (packed == g_max1[slot] || packed == g_max2[slot]) s = 1.0f;
    }

    int b  = g / PP;
    int p  = g - b * PP;
    int n  = p / HWSZ;
    int hw = p - n * HWSZ;

    size_t bn     = (size_t)(b * NV + n);
    size_t base_c = (bn * 3)  * HWSZ + hw;
    size_t base_r = (bn * 4)  * HWSZ + hw;
    size_t base_s = (bn * 12) * HWSZ + hw;

    float f[NCH];
    f[0] = mx; f[1] = my; f[2] = mz;
    f[3] = __ldcs(&cov[base_c]);
    f[4] = __ldcs(&cov[base_c + HWSZ]);
    f[5] = __ldcs(&cov[base_c + 2 * (size_t)HWSZ]);
#pragma unroll
    for (int i = 0; i < 4; i++)
        f[6 + i] = __ldcs(&rot[base_r + (size_t)i * HWSZ]);
    f[10] = opac[g];
#pragma unroll
    for (int i = 0; i < 12; i++)
        f[11 + i] = __ldcs(&sh[base_s + (size_t)i * HWSZ]);
    f[23] = conf[g];

#pragma unroll
    for (int i = 0; i < NCH; i++) f[i] *= s;

    float4* dst = reinterpret_cast<float4*>(out + (size_t)g * NCH);
#pragma unroll
    for (int i = 0; i < 6; i++)
        __stcs(dst + i, make_float4(f[4*i], f[4*i+1], f[4*i+2], f[4*i+3]));

    if (write_sel)
        __stcs(out + sel_off + (size_t)g, s);
}

// ---------------------------------------------------------------------------

extern "C" void kernel_launch(void* const* d_in, const int* in_sizes, int n_in,
                              void* d_out, int out_size) {
    const float* depth = (const float*)d_in[0];
    const float* cov   = (const float*)d_in[1];
    const float* rot   = (const float*)d_in[2];
    const float* opac  = (const float*)d_in[3];
    const float* sh    = (const float*)d_in[4];
    const float* conf  = (const float*)d_in[5];
    const float* poses = (const float*)d_in[6];
    float* out = (float*)d_out;

    size_t featN = (size_t)TOTAL * NCH;
    int write_sel = ((size_t)out_size >= featN + (size_t)TOTAL) ? 1 : 0;

    const int T = 256;
    clear_kernel<<<(CLEAR_THREADS + T - 1) / T, T>>>();
    pass1_kernel<<<(TOTAL + T - 1) / T, T>>>(depth, opac, conf, poses);
    pass3_kernel<<<(TOTAL + T - 1) / T, T>>>(depth, cov, rot, opac, sh, conf,
                                             poses, out, write_sel, featN);
}